// round 11
// baseline (speedup 1.0000x reference)
#include <cuda_runtime.h>
#include <cuda_fp16.h>
#include <cstdint>

#define DEV __device__ __forceinline__

// ----------------------------- constants -------------------------------------
constexpr int BATCH = 4096;
constexpr int DIM   = 2048;
constexpr int HL    = 3;

constexpr int TMT = 128;          // CTA M tile
constexpr int TNT = 128;          // CTA N tile
constexpr int TK  = 64;           // K per stage (64 halfs = 128 bytes/row)
constexpr int S   = 4;            // pipeline stages
constexpr int KSTG_PER_PASS = DIM / TK;          // 32
constexpr int NSTAGES      = 3 * KSTG_PER_PASS;  // 96 (3 split-precision passes)

constexpr int TILE_BYTES = 128 * 128;            // 16 KB per operand tile (128 rows x 128B)
constexpr int STG_BYTES  = 2 * TILE_BYTES;       // 32 KB (A + B)
constexpr int SMEM_TILES = 1024;                 // bias in [0,512)
constexpr int SMEM_SIZE  = SMEM_TILES + S * STG_BYTES;   // 132096 B

// ----------------------------- device scratch --------------------------------
__device__ __half g_Wh[(size_t)HL * DIM * DIM];
__device__ __half g_Wl[(size_t)HL * DIM * DIM];
__device__ float  g_bias[HL * DIM];
__device__ float  g_wo[DIM];
__device__ float  g_bo[1];
__device__ __half g_Ah0[(size_t)BATCH * DIM];
__device__ __half g_Al0[(size_t)BATCH * DIM];
__device__ __half g_Ah1[(size_t)BATCH * DIM];
__device__ __half g_Al1[(size_t)BATCH * DIM];
__device__ float  g_hf[(size_t)BATCH * DIM];     // fp32 output of last hidden layer

// ----------------------------- helpers ---------------------------------------
DEV uint32_t smem_u32(const void* p) { return (uint32_t)__cvta_generic_to_shared(p); }

DEV void cp_async16(uint32_t saddr, const void* gaddr) {
    asm volatile("cp.async.cg.shared.global [%0], [%1], 16;" :: "r"(saddr), "l"(gaddr) : "memory");
}
DEV void cp_commit() { asm volatile("cp.async.commit_group;" ::: "memory"); }
DEV void cp_wait2()  { asm volatile("cp.async.wait_group 2;" ::: "memory"); }

#define SW128(off) ((off) ^ (((off) >> 3) & 0x70))

DEV void ldsm_x4(uint32_t* r, uint32_t addr) {
    asm volatile("ldmatrix.sync.aligned.m8n8.x4.shared.b16 {%0,%1,%2,%3}, [%4];"
                 : "=r"(r[0]), "=r"(r[1]), "=r"(r[2]), "=r"(r[3]) : "r"(addr));
}

DEV void mma_f16(float* d, const uint32_t* a, const uint32_t* b) {
    asm volatile("mma.sync.aligned.m16n8k16.row.col.f32.f16.f16.f32 "
                 "{%0,%1,%2,%3}, {%4,%5,%6,%7}, {%8,%9}, {%0,%1,%2,%3};"
                 : "+f"(d[0]), "+f"(d[1]), "+f"(d[2]), "+f"(d[3])
                 : "r"(a[0]), "r"(a[1]), "r"(a[2]), "r"(a[3]), "r"(b[0]), "r"(b[1]));
}

DEV float softplus_f(float x) { return x > 20.f ? x : log1pf(expf(x)); }

DEV void split_hl(float v, __half& h, __half& l) {
    h = __float2half_rn(v);
    l = __float2half_rn(v - __half2float(h));
}

// ----------------------------- materialization -------------------------------
// W = mu + eps * softplus(rho)  ->  (Wh, Wl) fp16 hi/lo split
__global__ void vn_mat_w(const float4* __restrict__ mu, const float4* __restrict__ rho,
                         const float4* __restrict__ eps) {
    size_t i = (size_t)blockIdx.x * blockDim.x + threadIdx.x;   // exact: HL*D*D/4
    float4 m = mu[i], r = rho[i], e = eps[i];
    float w0 = fmaf(e.x, softplus_f(r.x), m.x);
    float w1 = fmaf(e.y, softplus_f(r.y), m.y);
    float w2 = fmaf(e.z, softplus_f(r.z), m.z);
    float w3 = fmaf(e.w, softplus_f(r.w), m.w);
    __half h0, l0, h1, l1, h2, l2, h3, l3;
    split_hl(w0, h0, l0); split_hl(w1, h1, l1);
    split_hl(w2, h2, l2); split_hl(w3, h3, l3);
    __half2* Wh = reinterpret_cast<__half2*>(g_Wh);
    __half2* Wl = reinterpret_cast<__half2*>(g_Wl);
    Wh[i * 2]     = __halves2half2(h0, h1);
    Wh[i * 2 + 1] = __halves2half2(h2, h3);
    Wl[i * 2]     = __halves2half2(l0, l1);
    Wl[i * 2 + 1] = __halves2half2(l2, l3);
}

__global__ void vn_mat_vec(const float* __restrict__ mu, const float* __restrict__ rho,
                           const float* __restrict__ eps, int dst_sel, int n) {
    float* dst = dst_sel == 0 ? g_bias : (dst_sel == 1 ? g_wo : g_bo);
    int i = blockIdx.x * blockDim.x + threadIdx.x;
    if (i < n) dst[i] = fmaf(eps[i], softplus_f(rho[i]), mu[i]);
}

// x -> (Ah0, Al0) fp16 hi/lo split
__global__ void vn_split_x(const float4* __restrict__ x) {
    size_t i = (size_t)blockIdx.x * blockDim.x + threadIdx.x;   // exact: B*D/4
    float4 v = x[i];
    __half h0, l0, h1, l1, h2, l2, h3, l3;
    split_hl(v.x, h0, l0); split_hl(v.y, h1, l1);
    split_hl(v.z, h2, l2); split_hl(v.w, h3, l3);
    __half2* Ah = reinterpret_cast<__half2*>(g_Ah0);
    __half2* Al = reinterpret_cast<__half2*>(g_Al0);
    Ah[i * 2]     = __halves2half2(h0, h1);
    Ah[i * 2 + 1] = __halves2half2(h2, h3);
    Al[i * 2]     = __halves2half2(l0, l1);
    Al[i * 2 + 1] = __halves2half2(l2, l3);
}

// ----------------------------- GEMM ------------------------------------------
// C = relu(A @ W^T + bias) via 3-pass split-fp16: Ah*Wh + Al*Wh + Ah*Wl.
// Output: fp16 hi/lo split (next layer input) or fp32 (last layer).
__global__ void __launch_bounds__(256, 1) vn_gemm(int layer, int asel, int wf32) {
    extern __shared__ char smem[];
    float* sbias = reinterpret_cast<float*>(smem);
    const uint32_t sb_tiles = smem_u32(smem) + SMEM_TILES;

    const int tid  = threadIdx.x;
    const int lane = tid & 31, wid = tid >> 5;
    const int wm = wid >> 2;          // 0..1  (64-row slab)
    const int wn = wid & 3;           // 0..3  (32-col slab)
    const int ntile = blockIdx.x, mtile = blockIdx.y;

    const __half* __restrict__ Ah = asel ? g_Ah1 : g_Ah0;
    const __half* __restrict__ Al = asel ? g_Al1 : g_Al0;
    const __half* __restrict__ Wh = g_Wh + (size_t)layer * DIM * DIM;
    const __half* __restrict__ Wl = g_Wl + (size_t)layer * DIM * DIM;
    __half* __restrict__ oAh = asel ? g_Ah0 : g_Ah1;
    __half* __restrict__ oAl = asel ? g_Al0 : g_Al1;
    const float* __restrict__ bias = g_bias + layer * DIM + ntile * TNT;

    if (tid < TNT) sbias[tid] = bias[tid];
    __syncthreads();

    // pass table: (Ah,Wh), (Al,Wh), (Ah,Wl)
    const char* Abase[3];
    const char* Bbase[3];
    {
        const size_t aoff = (size_t)mtile * TMT * DIM * 2;
        const size_t boff = (size_t)ntile * TNT * DIM * 2;
        Abase[0] = (const char*)Ah + aoff;  Bbase[0] = (const char*)Wh + boff;
        Abase[1] = (const char*)Al + aoff;  Bbase[1] = (const char*)Wh + boff;
        Abase[2] = (const char*)Ah + aoff;  Bbase[2] = (const char*)Wl + boff;
    }

    auto load_stage = [&](int st) {
        const int p  = st >> 5;                 // pass 0..2
        const int kk = (st & 31) * TK;          // k offset in halfs
        const int slot = st & (S - 1);
        const uint32_t sA = sb_tiles + slot * STG_BYTES;
        const uint32_t sB = sA + TILE_BYTES;
        const char* gA = Abase[p] + (size_t)kk * 2;
        const char* gB = Bbase[p] + (size_t)kk * 2;
#pragma unroll
        for (int j = 0; j < 4; j++) {           // A: 1024 16B granules / 256 thr
            int g = tid + j * 256, row = g >> 3, c = g & 7;
            cp_async16(sA + SW128(row * 128 + c * 16), gA + (size_t)row * (DIM * 2) + c * 16);
        }
#pragma unroll
        for (int j = 0; j < 4; j++) {           // B: 1024 granules
            int g = tid + j * 256, row = g >> 3, c = g & 7;
            cp_async16(sB + SW128(row * 128 + c * 16), gB + (size_t)row * (DIM * 2) + c * 16);
        }
    };

    // ldmatrix per-thread address components
    // A (x4 per m16 tile): mats (m0-7,k0-7)(m8-15,k0-7)(m0-7,k8-15)(m8-15,k8-15)
    uint32_t a_row[4], a_xor[4];
    const int a_kb = ((lane >> 4) & 1) * 16;
#pragma unroll
    for (int mt = 0; mt < 4; mt++) {
        int rl = wm * 64 + mt * 16 + ((lane >> 3) & 1) * 8 + (lane & 7);
        a_row[mt] = rl * 128;
        a_xor[mt] = (rl & 7) << 4;
    }
    // B (x4 per pair of n8 tiles): mats (n0-7,k0-7)(n0-7,k8-15)(n8-15,k0-7)(n8-15,k8-15)
    uint32_t b_row[2], b_xor[2];
    const int b_kb = ((lane >> 3) & 1) * 16;
#pragma unroll
    for (int j = 0; j < 2; j++) {
        int nl = wn * 32 + j * 16 + ((lane >> 4) & 1) * 8 + (lane & 7);
        b_row[j] = nl * 128;
        b_xor[j] = (nl & 7) << 4;
    }

    float acc[4][4][4];
#pragma unroll
    for (int i = 0; i < 4; i++)
#pragma unroll
        for (int j = 0; j < 4; j++)
#pragma unroll
            for (int c = 0; c < 4; c++) acc[i][j][c] = 0.f;

    for (int st = 0; st < S - 1; ++st) { load_stage(st); cp_commit(); }

    for (int s = 0; s < NSTAGES; ++s) {
        cp_wait2();
        __syncthreads();
        if (s + S - 1 < NSTAGES) load_stage(s + S - 1);
        cp_commit();

        const int slot = s & (S - 1);
        const uint32_t sA = sb_tiles + slot * STG_BYTES;
        const uint32_t sB = sA + TILE_BYTES;
#pragma unroll
        for (int ks = 0; ks < 4; ks++) {
            uint32_t afr[4][4], bfr[2][4];
#pragma unroll
            for (int mt = 0; mt < 4; mt++)
                ldsm_x4(afr[mt], sA + a_row[mt] + ((ks * 32 + a_kb) ^ a_xor[mt]));
#pragma unroll
            for (int j = 0; j < 2; j++)
                ldsm_x4(bfr[j], sB + b_row[j] + ((ks * 32 + b_kb) ^ b_xor[j]));
#pragma unroll
            for (int mt = 0; mt < 4; mt++)
#pragma unroll
                for (int nt = 0; nt < 4; nt++)
                    mma_f16(acc[mt][nt], afr[mt], &bfr[nt >> 1][(nt & 1) * 2]);
        }
    }

    // ---------------- epilogue: bias + relu, split-fp16 or fp32 ----------------
#pragma unroll
    for (int mt = 0; mt < 4; mt++) {
#pragma unroll
        for (int nt = 0; nt < 4; nt++) {
            const int rowg = mtile * TMT + wm * 64 + mt * 16 + (lane >> 2);
            const int coll = wn * 32 + nt * 8 + 2 * (lane & 3);
            const int colg = ntile * TNT + coll;
            float b0 = sbias[coll], b1 = sbias[coll + 1];
            float v0 = fmaxf(acc[mt][nt][0] + b0, 0.f);
            float v1 = fmaxf(acc[mt][nt][1] + b1, 0.f);
            float v2 = fmaxf(acc[mt][nt][2] + b0, 0.f);
            float v3 = fmaxf(acc[mt][nt][3] + b1, 0.f);
            if (wf32) {
                *reinterpret_cast<float2*>(g_hf + (size_t)rowg * DIM + colg)       = make_float2(v0, v1);
                *reinterpret_cast<float2*>(g_hf + (size_t)(rowg + 8) * DIM + colg) = make_float2(v2, v3);
            } else {
                __half h0, l0, h1, l1, h2, l2, h3, l3;
                split_hl(v0, h0, l0); split_hl(v1, h1, l1);
                split_hl(v2, h2, l2); split_hl(v3, h3, l3);
                *reinterpret_cast<__half2*>(oAh + (size_t)rowg * DIM + colg)       = __halves2half2(h0, h1);
                *reinterpret_cast<__half2*>(oAl + (size_t)rowg * DIM + colg)       = __halves2half2(l0, l1);
                *reinterpret_cast<__half2*>(oAh + (size_t)(rowg + 8) * DIM + colg) = __halves2half2(h2, h3);
                *reinterpret_cast<__half2*>(oAl + (size_t)(rowg + 8) * DIM + colg) = __halves2half2(l2, l3);
            }
        }
    }
}

// ----------------------------- output layer (exact fp32) ---------------------
__global__ void __launch_bounds__(256) vn_out(float* __restrict__ out) {
    const int wid = threadIdx.x >> 5, lid = threadIdx.x & 31;
    const int row = blockIdx.x * 8 + wid;
    const float4* h = reinterpret_cast<const float4*>(g_hf + (size_t)row * DIM);
    const float4* w = reinterpret_cast<const float4*>(g_wo);
    float acc = 0.f;
#pragma unroll
    for (int j = 0; j < 16; j++) {
        float4 a = h[lid + 32 * j], b = w[lid + 32 * j];
        acc += a.x * b.x + a.y * b.y + a.z * b.z + a.w * b.w;
    }
#pragma unroll
    for (int o = 16; o; o >>= 1) acc += __shfl_xor_sync(0xFFFFFFFFu, acc, o);
    if (lid == 0) out[row] = acc + g_bo[0];
}

// ----------------------------- launch ----------------------------------------
extern "C" void kernel_launch(void* const* d_in, const int* in_sizes, int n_in,
                              void* d_out, int out_size) {
    (void)in_sizes; (void)n_in; (void)out_size;
    cudaFuncSetAttribute(vn_gemm, cudaFuncAttributeMaxDynamicSharedMemorySize, SMEM_SIZE);

    // input order: x, w_mu_h, w_rho_h, b_mu_h, b_rho_h, w_mu_o, w_rho_o,
    //              b_mu_o, b_rho_o, eps_w_h, eps_b_h, eps_w_o, eps_b_o
    vn_mat_w<<<(HL * DIM * DIM / 4) / 256, 256>>>(
        (const float4*)d_in[1], (const float4*)d_in[2], (const float4*)d_in[9]);
    vn_mat_vec<<<(HL * DIM + 255) / 256, 256>>>(
        (const float*)d_in[3], (const float*)d_in[4], (const float*)d_in[10], 0, HL * DIM);
    vn_mat_vec<<<(DIM + 255) / 256, 256>>>(
        (const float*)d_in[5], (const float*)d_in[6], (const float*)d_in[11], 1, DIM);
    vn_mat_vec<<<1, 256>>>(
        (const float*)d_in[7], (const float*)d_in[8], (const float*)d_in[12], 2, 1);
    vn_split_x<<<(BATCH * DIM / 4) / 256, 256>>>((const float4*)d_in[0]);

    dim3 grid(DIM / TNT, BATCH / TMT);   // (16, 32)
    vn_gemm<<<grid, 256, SMEM_SIZE>>>(0, 0, 0);   // A0 -> A1 (fp16 split)
    vn_gemm<<<grid, 256, SMEM_SIZE>>>(1, 1, 0);   // A1 -> A0 (fp16 split)
    vn_gemm<<<grid, 256, SMEM_SIZE>>>(2, 0, 1);   // A0 -> g_hf (fp32)

    vn_out<<<BATCH / 8, 256>>>((float*)d_out);
}

// round 13
// speedup vs baseline: 1.0018x; 1.0018x over previous
#include <cuda_runtime.h>
#include <cuda_fp16.h>
#include <cstdint>

#define DEV __device__ __forceinline__

// ----------------------------- constants -------------------------------------
constexpr int BATCH = 4096;
constexpr int DIM   = 2048;
constexpr int HL    = 3;

constexpr int TMT = 128;          // CTA M tile
constexpr int TNT = 128;          // CTA N tile
constexpr int TK  = 64;           // K per stage (64 halfs = 128 bytes/row)
constexpr int S   = 4;            // pipeline stages
constexpr int KSTG_PER_PASS = DIM / TK;          // 32
constexpr int NSTAGES      = 3 * KSTG_PER_PASS;  // 96 (3 split-precision passes)

constexpr int TILE_BYTES = 128 * 128;            // 16 KB per operand tile (128 rows x 128B)
constexpr int STG_BYTES  = 2 * TILE_BYTES;       // 32 KB (A + B)
constexpr int SMEM_TILES = 1024;                 // bias in [0,512)
constexpr int SMEM_SIZE  = SMEM_TILES + S * STG_BYTES;   // 132096 B

// ----------------------------- device scratch --------------------------------
__device__ __half g_Wh[(size_t)HL * DIM * DIM];
__device__ __half g_Wl[(size_t)HL * DIM * DIM];
__device__ float  g_bias[HL * DIM];
__device__ float  g_wo[DIM];
__device__ float  g_bo[1];
__device__ __half g_Ah0[(size_t)BATCH * DIM];
__device__ __half g_Al0[(size_t)BATCH * DIM];
__device__ __half g_Ah1[(size_t)BATCH * DIM];
__device__ __half g_Al1[(size_t)BATCH * DIM];
__device__ float  g_hf[(size_t)BATCH * DIM];     // fp32 output of last hidden layer

// ----------------------------- helpers ---------------------------------------
DEV uint32_t smem_u32(const void* p) { return (uint32_t)__cvta_generic_to_shared(p); }

DEV void cp_async16(uint32_t saddr, const void* gaddr) {
    asm volatile("cp.async.cg.shared.global [%0], [%1], 16;" :: "r"(saddr), "l"(gaddr) : "memory");
}
DEV void cp_commit() { asm volatile("cp.async.commit_group;" ::: "memory"); }
DEV void cp_wait2()  { asm volatile("cp.async.wait_group 2;" ::: "memory"); }

#define SW128(off) ((off) ^ (((off) >> 3) & 0x70))

DEV void ldsm_x4(uint32_t* r, uint32_t addr) {
    asm volatile("ldmatrix.sync.aligned.m8n8.x4.shared.b16 {%0,%1,%2,%3}, [%4];"
                 : "=r"(r[0]), "=r"(r[1]), "=r"(r[2]), "=r"(r[3]) : "r"(addr));
}

DEV void mma_f16(float* d, const uint32_t* a, const uint32_t* b) {
    asm volatile("mma.sync.aligned.m16n8k16.row.col.f32.f16.f16.f32 "
                 "{%0,%1,%2,%3}, {%4,%5,%6,%7}, {%8,%9}, {%0,%1,%2,%3};"
                 : "+f"(d[0]), "+f"(d[1]), "+f"(d[2]), "+f"(d[3])
                 : "r"(a[0]), "r"(a[1]), "r"(a[2]), "r"(a[3]), "r"(b[0]), "r"(b[1]));
}

DEV float softplus_f(float x) { return x > 20.f ? x : log1pf(expf(x)); }

DEV void split_hl(float v, __half& h, __half& l) {
    h = __float2half_rn(v);
    l = __float2half_rn(v - __half2float(h));
}

// ----------------------------- materialization -------------------------------
// W = mu + eps * softplus(rho)  ->  (Wh, Wl) fp16 hi/lo split
__global__ void vn_mat_w(const float4* __restrict__ mu, const float4* __restrict__ rho,
                         const float4* __restrict__ eps) {
    size_t i = (size_t)blockIdx.x * blockDim.x + threadIdx.x;   // exact: HL*D*D/4
    float4 m = mu[i], r = rho[i], e = eps[i];
    float w0 = fmaf(e.x, softplus_f(r.x), m.x);
    float w1 = fmaf(e.y, softplus_f(r.y), m.y);
    float w2 = fmaf(e.z, softplus_f(r.z), m.z);
    float w3 = fmaf(e.w, softplus_f(r.w), m.w);
    __half h0, l0, h1, l1, h2, l2, h3, l3;
    split_hl(w0, h0, l0); split_hl(w1, h1, l1);
    split_hl(w2, h2, l2); split_hl(w3, h3, l3);
    __half2* Wh = reinterpret_cast<__half2*>(g_Wh);
    __half2* Wl = reinterpret_cast<__half2*>(g_Wl);
    Wh[i * 2]     = __halves2half2(h0, h1);
    Wh[i * 2 + 1] = __halves2half2(h2, h3);
    Wl[i * 2]     = __halves2half2(l0, l1);
    Wl[i * 2 + 1] = __halves2half2(l2, l3);
}

__global__ void vn_mat_vec(const float* __restrict__ mu, const float* __restrict__ rho,
                           const float* __restrict__ eps, int dst_sel, int n) {
    float* dst = dst_sel == 0 ? g_bias : (dst_sel == 1 ? g_wo : g_bo);
    int i = blockIdx.x * blockDim.x + threadIdx.x;
    if (i < n) dst[i] = fmaf(eps[i], softplus_f(rho[i]), mu[i]);
}

// x -> (Ah0, Al0) fp16 hi/lo split
__global__ void vn_split_x(const float4* __restrict__ x) {
    size_t i = (size_t)blockIdx.x * blockDim.x + threadIdx.x;   // exact: B*D/4
    float4 v = x[i];
    __half h0, l0, h1, l1, h2, l2, h3, l3;
    split_hl(v.x, h0, l0); split_hl(v.y, h1, l1);
    split_hl(v.z, h2, l2); split_hl(v.w, h3, l3);
    __half2* Ah = reinterpret_cast<__half2*>(g_Ah0);
    __half2* Al = reinterpret_cast<__half2*>(g_Al0);
    Ah[i * 2]     = __halves2half2(h0, h1);
    Ah[i * 2 + 1] = __halves2half2(h2, h3);
    Al[i * 2]     = __halves2half2(l0, l1);
    Al[i * 2 + 1] = __halves2half2(l2, l3);
}

// ----------------------------- GEMM ------------------------------------------
// C = relu(A @ W^T + bias) via 3-pass split-fp16: Ah*Wh + Al*Wh + Ah*Wl.
// Output: fp16 hi/lo split (next layer input) or fp32 (last layer).
__global__ void __launch_bounds__(256, 1) vn_gemm(int layer, int asel, int wf32) {
    extern __shared__ char smem[];
    float* sbias = reinterpret_cast<float*>(smem);
    const uint32_t sb_tiles = smem_u32(smem) + SMEM_TILES;

    const int tid  = threadIdx.x;
    const int lane = tid & 31, wid = tid >> 5;
    const int wm = wid >> 2;          // 0..1  (64-row slab)
    const int wn = wid & 3;           // 0..3  (32-col slab)
    const int ntile = blockIdx.x, mtile = blockIdx.y;

    const __half* __restrict__ Ah = asel ? g_Ah1 : g_Ah0;
    const __half* __restrict__ Al = asel ? g_Al1 : g_Al0;
    const __half* __restrict__ Wh = g_Wh + (size_t)layer * DIM * DIM;
    const __half* __restrict__ Wl = g_Wl + (size_t)layer * DIM * DIM;
    __half* __restrict__ oAh = asel ? g_Ah0 : g_Ah1;
    __half* __restrict__ oAl = asel ? g_Al0 : g_Al1;
    const float* __restrict__ bias = g_bias + layer * DIM + ntile * TNT;

    if (tid < TNT) sbias[tid] = bias[tid];
    __syncthreads();

    // pass table: (Ah,Wh), (Al,Wh), (Ah,Wl)
    const char* Abase[3];
    const char* Bbase[3];
    {
        const size_t aoff = (size_t)mtile * TMT * DIM * 2;
        const size_t boff = (size_t)ntile * TNT * DIM * 2;
        Abase[0] = (const char*)Ah + aoff;  Bbase[0] = (const char*)Wh + boff;
        Abase[1] = (const char*)Al + aoff;  Bbase[1] = (const char*)Wh + boff;
        Abase[2] = (const char*)Ah + aoff;  Bbase[2] = (const char*)Wl + boff;
    }

    auto load_stage = [&](int st) {
        const int p  = st >> 5;                 // pass 0..2
        const int kk = (st & 31) * TK;          // k offset in halfs
        const int slot = st & (S - 1);
        const uint32_t sA = sb_tiles + slot * STG_BYTES;
        const uint32_t sB = sA + TILE_BYTES;
        const char* gA = Abase[p] + (size_t)kk * 2;
        const char* gB = Bbase[p] + (size_t)kk * 2;
#pragma unroll
        for (int j = 0; j < 4; j++) {           // A: 1024 16B granules / 256 thr
            int g = tid + j * 256, row = g >> 3, c = g & 7;
            cp_async16(sA + SW128(row * 128 + c * 16), gA + (size_t)row * (DIM * 2) + c * 16);
        }
#pragma unroll
        for (int j = 0; j < 4; j++) {           // B: 1024 granules
            int g = tid + j * 256, row = g >> 3, c = g & 7;
            cp_async16(sB + SW128(row * 128 + c * 16), gB + (size_t)row * (DIM * 2) + c * 16);
        }
    };

    // ldmatrix per-thread address components
    // A (x4 per m16 tile): mats (m0-7,k0-7)(m8-15,k0-7)(m0-7,k8-15)(m8-15,k8-15)
    uint32_t a_row[4], a_xor[4];
    const int a_kb = ((lane >> 4) & 1) * 16;
#pragma unroll
    for (int mt = 0; mt < 4; mt++) {
        int rl = wm * 64 + mt * 16 + ((lane >> 3) & 1) * 8 + (lane & 7);
        a_row[mt] = rl * 128;
        a_xor[mt] = (rl & 7) << 4;
    }
    // B (x4 per pair of n8 tiles): mats (n0-7,k0-7)(n0-7,k8-15)(n8-15,k0-7)(n8-15,k8-15)
    uint32_t b_row[2], b_xor[2];
    const int b_kb = ((lane >> 3) & 1) * 16;
#pragma unroll
    for (int j = 0; j < 2; j++) {
        int nl = wn * 32 + j * 16 + ((lane >> 4) & 1) * 8 + (lane & 7);
        b_row[j] = nl * 128;
        b_xor[j] = (nl & 7) << 4;
    }

    float acc[4][4][4];
#pragma unroll
    for (int i = 0; i < 4; i++)
#pragma unroll
        for (int j = 0; j < 4; j++)
#pragma unroll
            for (int c = 0; c < 4; c++) acc[i][j][c] = 0.f;

    for (int st = 0; st < S - 1; ++st) { load_stage(st); cp_commit(); }

    for (int s = 0; s < NSTAGES; ++s) {
        cp_wait2();
        __syncthreads();
        if (s + S - 1 < NSTAGES) load_stage(s + S - 1);
        cp_commit();

        const int slot = s & (S - 1);
        const uint32_t sA = sb_tiles + slot * STG_BYTES;
        const uint32_t sB = sA + TILE_BYTES;
#pragma unroll
        for (int ks = 0; ks < 4; ks++) {
            uint32_t afr[4][4], bfr[2][4];
#pragma unroll
            for (int mt = 0; mt < 4; mt++)
                ldsm_x4(afr[mt], sA + a_row[mt] + ((ks * 32 + a_kb) ^ a_xor[mt]));
#pragma unroll
            for (int j = 0; j < 2; j++)
                ldsm_x4(bfr[j], sB + b_row[j] + ((ks * 32 + b_kb) ^ b_xor[j]));
#pragma unroll
            for (int mt = 0; mt < 4; mt++)
#pragma unroll
                for (int nt = 0; nt < 4; nt++)
                    mma_f16(acc[mt][nt], afr[mt], &bfr[nt >> 1][(nt & 1) * 2]);
        }
    }

    // ---------------- epilogue: bias + relu, split-fp16 or fp32 ----------------
#pragma unroll
    for (int mt = 0; mt < 4; mt++) {
#pragma unroll
        for (int nt = 0; nt < 4; nt++) {
            const int rowg = mtile * TMT + wm * 64 + mt * 16 + (lane >> 2);
            const int coll = wn * 32 + nt * 8 + 2 * (lane & 3);
            const int colg = ntile * TNT + coll;
            float b0 = sbias[coll], b1 = sbias[coll + 1];
            float v0 = fmaxf(acc[mt][nt][0] + b0, 0.f);
            float v1 = fmaxf(acc[mt][nt][1] + b1, 0.f);
            float v2 = fmaxf(acc[mt][nt][2] + b0, 0.f);
            float v3 = fmaxf(acc[mt][nt][3] + b1, 0.f);
            if (wf32) {
                *reinterpret_cast<float2*>(g_hf + (size_t)rowg * DIM + colg)       = make_float2(v0, v1);
                *reinterpret_cast<float2*>(g_hf + (size_t)(rowg + 8) * DIM + colg) = make_float2(v2, v3);
            } else {
                __half h0, l0, h1, l1, h2, l2, h3, l3;
                split_hl(v0, h0, l0); split_hl(v1, h1, l1);
                split_hl(v2, h2, l2); split_hl(v3, h3, l3);
                *reinterpret_cast<__half2*>(oAh + (size_t)rowg * DIM + colg)       = __halves2half2(h0, h1);
                *reinterpret_cast<__half2*>(oAl + (size_t)rowg * DIM + colg)       = __halves2half2(l0, l1);
                *reinterpret_cast<__half2*>(oAh + (size_t)(rowg + 8) * DIM + colg) = __halves2half2(h2, h3);
                *reinterpret_cast<__half2*>(oAl + (size_t)(rowg + 8) * DIM + colg) = __halves2half2(l2, l3);
            }
        }
    }
}

// ----------------------------- output layer (exact fp32) ---------------------
__global__ void __launch_bounds__(256) vn_out(float* __restrict__ out) {
    const int wid = threadIdx.x >> 5, lid = threadIdx.x & 31;
    const int row = blockIdx.x * 8 + wid;
    const float4* h = reinterpret_cast<const float4*>(g_hf + (size_t)row * DIM);
    const float4* w = reinterpret_cast<const float4*>(g_wo);
    float acc = 0.f;
#pragma unroll
    for (int j = 0; j < 16; j++) {
        float4 a = h[lid + 32 * j], b = w[lid + 32 * j];
        acc += a.x * b.x + a.y * b.y + a.z * b.z + a.w * b.w;
    }
#pragma unroll
    for (int o = 16; o; o >>= 1) acc += __shfl_xor_sync(0xFFFFFFFFu, acc, o);
    if (lid == 0) out[row] = acc + g_bo[0];
}

// ----------------------------- launch ----------------------------------------
extern "C" void kernel_launch(void* const* d_in, const int* in_sizes, int n_in,
                              void* d_out, int out_size) {
    (void)in_sizes; (void)n_in; (void)out_size;
    cudaFuncSetAttribute(vn_gemm, cudaFuncAttributeMaxDynamicSharedMemorySize, SMEM_SIZE);

    // input order: x, w_mu_h, w_rho_h, b_mu_h, b_rho_h, w_mu_o, w_rho_o,
    //              b_mu_o, b_rho_o, eps_w_h, eps_b_h, eps_w_o, eps_b_o
    vn_mat_w<<<(HL * DIM * DIM / 4) / 256, 256>>>(
        (const float4*)d_in[1], (const float4*)d_in[2], (const float4*)d_in[9]);
    vn_mat_vec<<<(HL * DIM + 255) / 256, 256>>>(
        (const float*)d_in[3], (const float*)d_in[4], (const float*)d_in[10], 0, HL * DIM);
    vn_mat_vec<<<(DIM + 255) / 256, 256>>>(
        (const float*)d_in[5], (const float*)d_in[6], (const float*)d_in[11], 1, DIM);
    vn_mat_vec<<<1, 256>>>(
        (const float*)d_in[7], (const float*)d_in[8], (const float*)d_in[12], 2, 1);
    vn_split_x<<<(BATCH * DIM / 4) / 256, 256>>>((const float4*)d_in[0]);

    dim3 grid(DIM / TNT, BATCH / TMT);   // (16, 32)
    vn_gemm<<<grid, 256, SMEM_SIZE>>>(0, 0, 0);   // A0 -> A1 (fp16 split)
    vn_gemm<<<grid, 256, SMEM_SIZE>>>(1, 1, 0);   // A1 -> A0 (fp16 split)
    vn_gemm<<<grid, 256, SMEM_SIZE>>>(2, 0, 1);   // A0 -> g_hf (fp32)

    vn_out<<<BATCH / 8, 256>>>((float*)d_out);
}

// round 16
// speedup vs baseline: 1.0024x; 1.0006x over previous
#include <cuda_runtime.h>
#include <cuda_fp16.h>
#include <cstdint>

#define DEV __device__ __forceinline__

// ----------------------------- constants -------------------------------------
constexpr int BATCH = 4096;
constexpr int DIM   = 2048;
constexpr int HL    = 3;

constexpr int TMT = 128;          // CTA M tile
constexpr int TNT = 128;          // CTA N tile
constexpr int TK  = 64;           // K per stage (64 halfs = 128 bytes/row)
constexpr int S   = 4;            // pipeline stages
constexpr int KSTG_PER_PASS = DIM / TK;          // 32
constexpr int NSTAGES      = 3 * KSTG_PER_PASS;  // 96 (3 split-precision passes)

constexpr int TILE_BYTES = 128 * 128;            // 16 KB per operand tile (128 rows x 128B)
constexpr int STG_BYTES  = 2 * TILE_BYTES;       // 32 KB (A + B)
constexpr int SMEM_TILES = 1024;                 // bias in [0,512)
constexpr int SMEM_SIZE  = SMEM_TILES + S * STG_BYTES;   // 132096 B

// ----------------------------- device scratch --------------------------------
__device__ __half g_Wh[(size_t)HL * DIM * DIM];
__device__ __half g_Wl[(size_t)HL * DIM * DIM];
__device__ float  g_bias[HL * DIM];
__device__ float  g_wo[DIM];
__device__ float  g_bo[1];
__device__ __half g_Ah0[(size_t)BATCH * DIM];
__device__ __half g_Al0[(size_t)BATCH * DIM];
__device__ __half g_Ah1[(size_t)BATCH * DIM];
__device__ __half g_Al1[(size_t)BATCH * DIM];
__device__ float  g_hf[(size_t)BATCH * DIM];     // fp32 output of last hidden layer

// ----------------------------- helpers ---------------------------------------
DEV uint32_t smem_u32(const void* p) { return (uint32_t)__cvta_generic_to_shared(p); }

DEV void cp_async16(uint32_t saddr, const void* gaddr) {
    asm volatile("cp.async.cg.shared.global [%0], [%1], 16;" :: "r"(saddr), "l"(gaddr) : "memory");
}
DEV void cp_commit() { asm volatile("cp.async.commit_group;" ::: "memory"); }
DEV void cp_wait2()  { asm volatile("cp.async.wait_group 2;" ::: "memory"); }

#define SW128(off) ((off) ^ (((off) >> 3) & 0x70))

DEV void ldsm_x4(uint32_t* r, uint32_t addr) {
    asm volatile("ldmatrix.sync.aligned.m8n8.x4.shared.b16 {%0,%1,%2,%3}, [%4];"
                 : "=r"(r[0]), "=r"(r[1]), "=r"(r[2]), "=r"(r[3]) : "r"(addr));
}

DEV void mma_f16(float* d, const uint32_t* a, const uint32_t* b) {
    asm volatile("mma.sync.aligned.m16n8k16.row.col.f32.f16.f16.f32 "
                 "{%0,%1,%2,%3}, {%4,%5,%6,%7}, {%8,%9}, {%0,%1,%2,%3};"
                 : "+f"(d[0]), "+f"(d[1]), "+f"(d[2]), "+f"(d[3])
                 : "r"(a[0]), "r"(a[1]), "r"(a[2]), "r"(a[3]), "r"(b[0]), "r"(b[1]));
}

DEV float softplus_f(float x) { return x > 20.f ? x : log1pf(expf(x)); }

DEV void split_hl(float v, __half& h, __half& l) {
    h = __float2half_rn(v);
    l = __float2half_rn(v - __half2float(h));
}

// ----------------------------- materialization -------------------------------
// W = mu + eps * softplus(rho)  ->  (Wh, Wl) fp16 hi/lo split
__global__ void vn_mat_w(const float4* __restrict__ mu, const float4* __restrict__ rho,
                         const float4* __restrict__ eps) {
    size_t i = (size_t)blockIdx.x * blockDim.x + threadIdx.x;   // exact: HL*D*D/4
    float4 m = mu[i], r = rho[i], e = eps[i];
    float w0 = fmaf(e.x, softplus_f(r.x), m.x);
    float w1 = fmaf(e.y, softplus_f(r.y), m.y);
    float w2 = fmaf(e.z, softplus_f(r.z), m.z);
    float w3 = fmaf(e.w, softplus_f(r.w), m.w);
    __half h0, l0, h1, l1, h2, l2, h3, l3;
    split_hl(w0, h0, l0); split_hl(w1, h1, l1);
    split_hl(w2, h2, l2); split_hl(w3, h3, l3);
    __half2* Wh = reinterpret_cast<__half2*>(g_Wh);
    __half2* Wl = reinterpret_cast<__half2*>(g_Wl);
    Wh[i * 2]     = __halves2half2(h0, h1);
    Wh[i * 2 + 1] = __halves2half2(h2, h3);
    Wl[i * 2]     = __halves2half2(l0, l1);
    Wl[i * 2 + 1] = __halves2half2(l2, l3);
}

__global__ void vn_mat_vec(const float* __restrict__ mu, const float* __restrict__ rho,
                           const float* __restrict__ eps, int dst_sel, int n) {
    float* dst = dst_sel == 0 ? g_bias : (dst_sel == 1 ? g_wo : g_bo);
    int i = blockIdx.x * blockDim.x + threadIdx.x;
    if (i < n) dst[i] = fmaf(eps[i], softplus_f(rho[i]), mu[i]);
}

// x -> (Ah0, Al0) fp16 hi/lo split
__global__ void vn_split_x(const float4* __restrict__ x) {
    size_t i = (size_t)blockIdx.x * blockDim.x + threadIdx.x;   // exact: B*D/4
    float4 v = x[i];
    __half h0, l0, h1, l1, h2, l2, h3, l3;
    split_hl(v.x, h0, l0); split_hl(v.y, h1, l1);
    split_hl(v.z, h2, l2); split_hl(v.w, h3, l3);
    __half2* Ah = reinterpret_cast<__half2*>(g_Ah0);
    __half2* Al = reinterpret_cast<__half2*>(g_Al0);
    Ah[i * 2]     = __halves2half2(h0, h1);
    Ah[i * 2 + 1] = __halves2half2(h2, h3);
    Al[i * 2]     = __halves2half2(l0, l1);
    Al[i * 2 + 1] = __halves2half2(l2, l3);
}

// ----------------------------- GEMM ------------------------------------------
// C = relu(A @ W^T + bias) via 3-pass split-fp16: Ah*Wh + Al*Wh + Ah*Wl.
// Output: fp16 hi/lo split (next layer input) or fp32 (last layer).
__global__ void __launch_bounds__(256, 1) vn_gemm(int layer, int asel, int wf32) {
    extern __shared__ char smem[];
    float* sbias = reinterpret_cast<float*>(smem);
    const uint32_t sb_tiles = smem_u32(smem) + SMEM_TILES;

    const int tid  = threadIdx.x;
    const int lane = tid & 31, wid = tid >> 5;
    const int wm = wid >> 2;          // 0..1  (64-row slab)
    const int wn = wid & 3;           // 0..3  (32-col slab)
    const int ntile = blockIdx.x, mtile = blockIdx.y;

    const __half* __restrict__ Ah = asel ? g_Ah1 : g_Ah0;
    const __half* __restrict__ Al = asel ? g_Al1 : g_Al0;
    const __half* __restrict__ Wh = g_Wh + (size_t)layer * DIM * DIM;
    const __half* __restrict__ Wl = g_Wl + (size_t)layer * DIM * DIM;
    __half* __restrict__ oAh = asel ? g_Ah0 : g_Ah1;
    __half* __restrict__ oAl = asel ? g_Al0 : g_Al1;
    const float* __restrict__ bias = g_bias + layer * DIM + ntile * TNT;

    if (tid < TNT) sbias[tid] = bias[tid];
    __syncthreads();

    // pass table: (Ah,Wh), (Al,Wh), (Ah,Wl)
    const char* Abase[3];
    const char* Bbase[3];
    {
        const size_t aoff = (size_t)mtile * TMT * DIM * 2;
        const size_t boff = (size_t)ntile * TNT * DIM * 2;
        Abase[0] = (const char*)Ah + aoff;  Bbase[0] = (const char*)Wh + boff;
        Abase[1] = (const char*)Al + aoff;  Bbase[1] = (const char*)Wh + boff;
        Abase[2] = (const char*)Ah + aoff;  Bbase[2] = (const char*)Wl + boff;
    }

    auto load_stage = [&](int st) {
        const int p  = st >> 5;                 // pass 0..2
        const int kk = (st & 31) * TK;          // k offset in halfs
        const int slot = st & (S - 1);
        const uint32_t sA = sb_tiles + slot * STG_BYTES;
        const uint32_t sB = sA + TILE_BYTES;
        const char* gA = Abase[p] + (size_t)kk * 2;
        const char* gB = Bbase[p] + (size_t)kk * 2;
#pragma unroll
        for (int j = 0; j < 4; j++) {           // A: 1024 16B granules / 256 thr
            int g = tid + j * 256, row = g >> 3, c = g & 7;
            cp_async16(sA + SW128(row * 128 + c * 16), gA + (size_t)row * (DIM * 2) + c * 16);
        }
#pragma unroll
        for (int j = 0; j < 4; j++) {           // B: 1024 granules
            int g = tid + j * 256, row = g >> 3, c = g & 7;
            cp_async16(sB + SW128(row * 128 + c * 16), gB + (size_t)row * (DIM * 2) + c * 16);
        }
    };

    // ldmatrix per-thread address components
    // A (x4 per m16 tile): mats (m0-7,k0-7)(m8-15,k0-7)(m0-7,k8-15)(m8-15,k8-15)
    uint32_t a_row[4], a_xor[4];
    const int a_kb = ((lane >> 4) & 1) * 16;
#pragma unroll
    for (int mt = 0; mt < 4; mt++) {
        int rl = wm * 64 + mt * 16 + ((lane >> 3) & 1) * 8 + (lane & 7);
        a_row[mt] = rl * 128;
        a_xor[mt] = (rl & 7) << 4;
    }
    // B (x4 per pair of n8 tiles): mats (n0-7,k0-7)(n0-7,k8-15)(n8-15,k0-7)(n8-15,k8-15)
    uint32_t b_row[2], b_xor[2];
    const int b_kb = ((lane >> 3) & 1) * 16;
#pragma unroll
    for (int j = 0; j < 2; j++) {
        int nl = wn * 32 + j * 16 + ((lane >> 4) & 1) * 8 + (lane & 7);
        b_row[j] = nl * 128;
        b_xor[j] = (nl & 7) << 4;
    }

    float acc[4][4][4];
#pragma unroll
    for (int i = 0; i < 4; i++)
#pragma unroll
        for (int j = 0; j < 4; j++)
#pragma unroll
            for (int c = 0; c < 4; c++) acc[i][j][c] = 0.f;

    for (int st = 0; st < S - 1; ++st) { load_stage(st); cp_commit(); }

    for (int s = 0; s < NSTAGES; ++s) {
        cp_wait2();
        __syncthreads();
        if (s + S - 1 < NSTAGES) load_stage(s + S - 1);
        cp_commit();

        const int slot = s & (S - 1);
        const uint32_t sA = sb_tiles + slot * STG_BYTES;
        const uint32_t sB = sA + TILE_BYTES;
#pragma unroll
        for (int ks = 0; ks < 4; ks++) {
            uint32_t afr[4][4], bfr[2][4];
#pragma unroll
            for (int mt = 0; mt < 4; mt++)
                ldsm_x4(afr[mt], sA + a_row[mt] + ((ks * 32 + a_kb) ^ a_xor[mt]));
#pragma unroll
            for (int j = 0; j < 2; j++)
                ldsm_x4(bfr[j], sB + b_row[j] + ((ks * 32 + b_kb) ^ b_xor[j]));
#pragma unroll
            for (int mt = 0; mt < 4; mt++)
#pragma unroll
                for (int nt = 0; nt < 4; nt++)
                    mma_f16(acc[mt][nt], afr[mt], &bfr[nt >> 1][(nt & 1) * 2]);
        }
    }

    // ---------------- epilogue: bias + relu, split-fp16 or fp32 ----------------
#pragma unroll
    for (int mt = 0; mt < 4; mt++) {
#pragma unroll
        for (int nt = 0; nt < 4; nt++) {
            const int rowg = mtile * TMT + wm * 64 + mt * 16 + (lane >> 2);
            const int coll = wn * 32 + nt * 8 + 2 * (lane & 3);
            const int colg = ntile * TNT + coll;
            float b0 = sbias[coll], b1 = sbias[coll + 1];
            float v0 = fmaxf(acc[mt][nt][0] + b0, 0.f);
            float v1 = fmaxf(acc[mt][nt][1] + b1, 0.f);
            float v2 = fmaxf(acc[mt][nt][2] + b0, 0.f);
            float v3 = fmaxf(acc[mt][nt][3] + b1, 0.f);
            if (wf32) {
                *reinterpret_cast<float2*>(g_hf + (size_t)rowg * DIM + colg)       = make_float2(v0, v1);
                *reinterpret_cast<float2*>(g_hf + (size_t)(rowg + 8) * DIM + colg) = make_float2(v2, v3);
            } else {
                __half h0, l0, h1, l1, h2, l2, h3, l3;
                split_hl(v0, h0, l0); split_hl(v1, h1, l1);
                split_hl(v2, h2, l2); split_hl(v3, h3, l3);
                *reinterpret_cast<__half2*>(oAh + (size_t)rowg * DIM + colg)       = __halves2half2(h0, h1);
                *reinterpret_cast<__half2*>(oAl + (size_t)rowg * DIM + colg)       = __halves2half2(l0, l1);
                *reinterpret_cast<__half2*>(oAh + (size_t)(rowg + 8) * DIM + colg) = __halves2half2(h2, h3);
                *reinterpret_cast<__half2*>(oAl + (size_t)(rowg + 8) * DIM + colg) = __halves2half2(l2, l3);
            }
        }
    }
}

// ----------------------------- output layer (exact fp32) ---------------------
__global__ void __launch_bounds__(256) vn_out(float* __restrict__ out) {
    const int wid = threadIdx.x >> 5, lid = threadIdx.x & 31;
    const int row = blockIdx.x * 8 + wid;
    const float4* h = reinterpret_cast<const float4*>(g_hf + (size_t)row * DIM);
    const float4* w = reinterpret_cast<const float4*>(g_wo);
    float acc = 0.f;
#pragma unroll
    for (int j = 0; j < 16; j++) {
        float4 a = h[lid + 32 * j], b = w[lid + 32 * j];
        acc += a.x * b.x + a.y * b.y + a.z * b.z + a.w * b.w;
    }
#pragma unroll
    for (int o = 16; o; o >>= 1) acc += __shfl_xor_sync(0xFFFFFFFFu, acc, o);
    if (lid == 0) out[row] = acc + g_bo[0];
}

// ----------------------------- launch ----------------------------------------
extern "C" void kernel_launch(void* const* d_in, const int* in_sizes, int n_in,
                              void* d_out, int out_size) {
    (void)in_sizes; (void)n_in; (void)out_size;
    cudaFuncSetAttribute(vn_gemm, cudaFuncAttributeMaxDynamicSharedMemorySize, SMEM_SIZE);

    // input order: x, w_mu_h, w_rho_h, b_mu_h, b_rho_h, w_mu_o, w_rho_o,
    //              b_mu_o, b_rho_o, eps_w_h, eps_b_h, eps_w_o, eps_b_o
    vn_mat_w<<<(HL * DIM * DIM / 4) / 256, 256>>>(
        (const float4*)d_in[1], (const float4*)d_in[2], (const float4*)d_in[9]);
    vn_mat_vec<<<(HL * DIM + 255) / 256, 256>>>(
        (const float*)d_in[3], (const float*)d_in[4], (const float*)d_in[10], 0, HL * DIM);
    vn_mat_vec<<<(DIM + 255) / 256, 256>>>(
        (const float*)d_in[5], (const float*)d_in[6], (const float*)d_in[11], 1, DIM);
    vn_mat_vec<<<1, 256>>>(
        (const float*)d_in[7], (const float*)d_in[8], (const float*)d_in[12], 2, 1);
    vn_split_x<<<(BATCH * DIM / 4) / 256, 256>>>((const float4*)d_in[0]);

    dim3 grid(DIM / TNT, BATCH / TMT);   // (16, 32)
    vn_gemm<<<grid, 256, SMEM_SIZE>>>(0, 0, 0);   // A0 -> A1 (fp16 split)
    vn_gemm<<<grid, 256, SMEM_SIZE>>>(1, 1, 0);   // A1 -> A0 (fp16 split)
    vn_gemm<<<grid, 256, SMEM_SIZE>>>(2, 0, 1);   // A0 -> g_hf (fp32)

    vn_out<<<BATCH / 8, 256>>>((float*)d_out);
}

// round 17
// speedup vs baseline: 1.6588x; 1.6548x over previous
#include <cuda_runtime.h>
#include <cuda_fp16.h>
#include <cstdint>

#define DEV __device__ __forceinline__

// ----------------------------- constants -------------------------------------
constexpr int BATCH = 4096;
constexpr int DIM   = 2048;
constexpr int HL    = 3;

constexpr int TMT = 128;          // CTA M tile
constexpr int TNT = 128;          // CTA N tile
constexpr int TK  = 64;           // K per stage (64 halfs = 128 bytes/row)
constexpr int S   = 3;            // pipeline stages
constexpr int NSTAGES = DIM / TK; // 32 k-stages (each does A*Wh + A*Wl)

constexpr int TILE_BYTES = 128 * 128;            // 16 KB per operand tile
constexpr int STG_BYTES  = 3 * TILE_BYTES;       // 48 KB (A + Wh + Wl)
constexpr int SMEM_TILES = 1024;                 // bias in [0,512)
constexpr int SMEM_SIZE  = SMEM_TILES + S * STG_BYTES;   // 148480 B

// ----------------------------- device scratch --------------------------------
__device__ __half g_Wh[(size_t)HL * DIM * DIM];
__device__ __half g_Wl[(size_t)HL * DIM * DIM];
__device__ float  g_bias[HL * DIM];
__device__ float  g_wo[DIM];
__device__ float  g_bo[1];
__device__ __half g_A0[(size_t)BATCH * DIM];     // fp16 activations (ping-pong)
__device__ __half g_A1[(size_t)BATCH * DIM];
__device__ float  g_hf[(size_t)BATCH * DIM];     // fp32 output of last hidden layer

// ----------------------------- helpers ---------------------------------------
DEV uint32_t smem_u32(const void* p) { return (uint32_t)__cvta_generic_to_shared(p); }

DEV void cp_async16(uint32_t saddr, const void* gaddr) {
    asm volatile("cp.async.cg.shared.global [%0], [%1], 16;" :: "r"(saddr), "l"(gaddr) : "memory");
}
DEV void cp_commit() { asm volatile("cp.async.commit_group;" ::: "memory"); }
DEV void cp_wait1()  { asm volatile("cp.async.wait_group 1;" ::: "memory"); }

#define SW128(off) ((off) ^ (((off) >> 3) & 0x70))

DEV void ldsm_x4(uint32_t* r, uint32_t addr) {
    asm volatile("ldmatrix.sync.aligned.m8n8.x4.shared.b16 {%0,%1,%2,%3}, [%4];"
                 : "=r"(r[0]), "=r"(r[1]), "=r"(r[2]), "=r"(r[3]) : "r"(addr));
}

DEV void mma_f16(float* d, const uint32_t* a, const uint32_t* b) {
    asm volatile("mma.sync.aligned.m16n8k16.row.col.f32.f16.f16.f32 "
                 "{%0,%1,%2,%3}, {%4,%5,%6,%7}, {%8,%9}, {%0,%1,%2,%3};"
                 : "+f"(d[0]), "+f"(d[1]), "+f"(d[2]), "+f"(d[3])
                 : "r"(a[0]), "r"(a[1]), "r"(a[2]), "r"(a[3]), "r"(b[0]), "r"(b[1]));
}

DEV float softplus_f(float x) { return x > 20.f ? x : log1pf(expf(x)); }

DEV void split_hl(float v, __half& h, __half& l) {
    h = __float2half_rn(v);
    l = __float2half_rn(v - __half2float(h));
}

// ----------------------------- materialization -------------------------------
// W = mu + eps * softplus(rho)  ->  (Wh, Wl) fp16 hi/lo split (exact to ~2^-22)
__global__ void vn_mat_w(const float4* __restrict__ mu, const float4* __restrict__ rho,
                         const float4* __restrict__ eps) {
    size_t i = (size_t)blockIdx.x * blockDim.x + threadIdx.x;   // exact: HL*D*D/4
    float4 m = mu[i], r = rho[i], e = eps[i];
    float w0 = fmaf(e.x, softplus_f(r.x), m.x);
    float w1 = fmaf(e.y, softplus_f(r.y), m.y);
    float w2 = fmaf(e.z, softplus_f(r.z), m.z);
    float w3 = fmaf(e.w, softplus_f(r.w), m.w);
    __half h0, l0, h1, l1, h2, l2, h3, l3;
    split_hl(w0, h0, l0); split_hl(w1, h1, l1);
    split_hl(w2, h2, l2); split_hl(w3, h3, l3);
    __half2* Wh = reinterpret_cast<__half2*>(g_Wh);
    __half2* Wl = reinterpret_cast<__half2*>(g_Wl);
    Wh[i * 2]     = __halves2half2(h0, h1);
    Wh[i * 2 + 1] = __halves2half2(h2, h3);
    Wl[i * 2]     = __halves2half2(l0, l1);
    Wl[i * 2 + 1] = __halves2half2(l2, l3);
}

__global__ void vn_mat_vec(const float* __restrict__ mu, const float* __restrict__ rho,
                           const float* __restrict__ eps, int dst_sel, int n) {
    float* dst = dst_sel == 0 ? g_bias : (dst_sel == 1 ? g_wo : g_bo);
    int i = blockIdx.x * blockDim.x + threadIdx.x;
    if (i < n) dst[i] = fmaf(eps[i], softplus_f(rho[i]), mu[i]);
}

// x -> fp16 (rn)
__global__ void vn_x16(const float4* __restrict__ x) {
    size_t i = (size_t)blockIdx.x * blockDim.x + threadIdx.x;   // exact: B*D/4
    float4 v = x[i];
    __half2* A = reinterpret_cast<__half2*>(g_A0);
    A[i * 2]     = __floats2half2_rn(v.x, v.y);
    A[i * 2 + 1] = __floats2half2_rn(v.z, v.w);
}

// ----------------------------- GEMM ------------------------------------------
// C = relu(A @ W^T + bias), W = Wh + Wl (both fp16), A fp16.
// Each k-stage accumulates A*Wh + A*Wl into the same fp32 accumulators.
__global__ void __launch_bounds__(256, 1) vn_gemm(int layer, int asel, int wf32) {
    extern __shared__ char smem[];
    float* sbias = reinterpret_cast<float*>(smem);
    const uint32_t sb_tiles = smem_u32(smem) + SMEM_TILES;

    const int tid  = threadIdx.x;
    const int lane = tid & 31, wid = tid >> 5;
    const int wm = wid >> 2;          // 0..1  (64-row slab)
    const int wn = wid & 3;           // 0..3  (32-col slab)
    const int ntile = blockIdx.x, mtile = blockIdx.y;

    const __half* __restrict__ A  = asel ? g_A1 : g_A0;
    const __half* __restrict__ Wh = g_Wh + (size_t)layer * DIM * DIM;
    const __half* __restrict__ Wl = g_Wl + (size_t)layer * DIM * DIM;
    __half* __restrict__ oA = asel ? g_A0 : g_A1;
    const float* __restrict__ bias = g_bias + layer * DIM + ntile * TNT;

    if (tid < TNT) sbias[tid] = bias[tid];
    __syncthreads();

    const char* Abase  = (const char*)A  + (size_t)mtile * TMT * DIM * 2;
    const char* WhBase = (const char*)Wh + (size_t)ntile * TNT * DIM * 2;
    const char* WlBase = (const char*)Wl + (size_t)ntile * TNT * DIM * 2;

    auto load_stage = [&](int st) {
        const int slot = st % S;
        const uint32_t sA  = sb_tiles + slot * STG_BYTES;
        const uint32_t sBh = sA + TILE_BYTES;
        const uint32_t sBl = sA + 2 * TILE_BYTES;
        const size_t koff = (size_t)st * TK * 2;   // bytes into the K dim
        const char* gA  = Abase  + koff;
        const char* gBh = WhBase + koff;
        const char* gBl = WlBase + koff;
#pragma unroll
        for (int j = 0; j < 4; j++) {           // 1024 16B granules / 256 thr each tile
            int g = tid + j * 256, row = g >> 3, c = g & 7;
            uint32_t so = SW128(row * 128 + c * 16);
            size_t   go = (size_t)row * (DIM * 2) + c * 16;
            cp_async16(sA  + so, gA  + go);
            cp_async16(sBh + so, gBh + go);
            cp_async16(sBl + so, gBl + go);
        }
    };

    // ldmatrix per-thread address components (identical to proven R16 layout)
    uint32_t a_row[4], a_xor[4];
    const int a_kb = ((lane >> 4) & 1) * 16;
#pragma unroll
    for (int mt = 0; mt < 4; mt++) {
        int rl = wm * 64 + mt * 16 + ((lane >> 3) & 1) * 8 + (lane & 7);
        a_row[mt] = rl * 128;
        a_xor[mt] = (rl & 7) << 4;
    }
    uint32_t b_row[2], b_xor[2];
    const int b_kb = ((lane >> 3) & 1) * 16;
#pragma unroll
    for (int j = 0; j < 2; j++) {
        int nl = wn * 32 + j * 16 + ((lane >> 4) & 1) * 8 + (lane & 7);
        b_row[j] = nl * 128;
        b_xor[j] = (nl & 7) << 4;
    }

    float acc[4][4][4];
#pragma unroll
    for (int i = 0; i < 4; i++)
#pragma unroll
        for (int j = 0; j < 4; j++)
#pragma unroll
            for (int c = 0; c < 4; c++) acc[i][j][c] = 0.f;

    load_stage(0); cp_commit();
    load_stage(1); cp_commit();

    for (int s = 0; s < NSTAGES; ++s) {
        cp_wait1();
        __syncthreads();
        if (s + 2 < NSTAGES) load_stage(s + 2);
        cp_commit();

        const int slot = s % S;
        const uint32_t sA  = sb_tiles + slot * STG_BYTES;
        const uint32_t sBh = sA + TILE_BYTES;
        const uint32_t sBl = sA + 2 * TILE_BYTES;
#pragma unroll
        for (int ks = 0; ks < 4; ks++) {
            uint32_t afr[4][4], bh[2][4], bl[2][4];
#pragma unroll
            for (int mt = 0; mt < 4; mt++)
                ldsm_x4(afr[mt], sA + a_row[mt] + ((ks * 32 + a_kb) ^ a_xor[mt]));
#pragma unroll
            for (int j = 0; j < 2; j++) {
                ldsm_x4(bh[j], sBh + b_row[j] + ((ks * 32 + b_kb) ^ b_xor[j]));
                ldsm_x4(bl[j], sBl + b_row[j] + ((ks * 32 + b_kb) ^ b_xor[j]));
            }
#pragma unroll
            for (int mt = 0; mt < 4; mt++)
#pragma unroll
                for (int nt = 0; nt < 4; nt++)
                    mma_f16(acc[mt][nt], afr[mt], &bh[nt >> 1][(nt & 1) * 2]);
#pragma unroll
            for (int mt = 0; mt < 4; mt++)
#pragma unroll
                for (int nt = 0; nt < 4; nt++)
                    mma_f16(acc[mt][nt], afr[mt], &bl[nt >> 1][(nt & 1) * 2]);
        }
    }

    // ---------------- epilogue: bias + relu ----------------
#pragma unroll
    for (int mt = 0; mt < 4; mt++) {
#pragma unroll
        for (int nt = 0; nt < 4; nt++) {
            const int rowg = mtile * TMT + wm * 64 + mt * 16 + (lane >> 2);
            const int coll = wn * 32 + nt * 8 + 2 * (lane & 3);
            const int colg = ntile * TNT + coll;
            float b0 = sbias[coll], b1 = sbias[coll + 1];
            float v0 = fmaxf(acc[mt][nt][0] + b0, 0.f);
            float v1 = fmaxf(acc[mt][nt][1] + b1, 0.f);
            float v2 = fmaxf(acc[mt][nt][2] + b0, 0.f);
            float v3 = fmaxf(acc[mt][nt][3] + b1, 0.f);
            if (wf32) {
                *reinterpret_cast<float2*>(g_hf + (size_t)rowg * DIM + colg)       = make_float2(v0, v1);
                *reinterpret_cast<float2*>(g_hf + (size_t)(rowg + 8) * DIM + colg) = make_float2(v2, v3);
            } else {
                *reinterpret_cast<__half2*>(oA + (size_t)rowg * DIM + colg)       = __floats2half2_rn(v0, v1);
                *reinterpret_cast<__half2*>(oA + (size_t)(rowg + 8) * DIM + colg) = __floats2half2_rn(v2, v3);
            }
        }
    }
}

// ----------------------------- output layer (exact fp32) ---------------------
__global__ void __launch_bounds__(256) vn_out(float* __restrict__ out) {
    const int wid = threadIdx.x >> 5, lid = threadIdx.x & 31;
    const int row = blockIdx.x * 8 + wid;
    const float4* h = reinterpret_cast<const float4*>(g_hf + (size_t)row * DIM);
    const float4* w = reinterpret_cast<const float4*>(g_wo);
    float acc = 0.f;
#pragma unroll
    for (int j = 0; j < 16; j++) {
        float4 a = h[lid + 32 * j], b = w[lid + 32 * j];
        acc += a.x * b.x + a.y * b.y + a.z * b.z + a.w * b.w;
    }
#pragma unroll
    for (int o = 16; o; o >>= 1) acc += __shfl_xor_sync(0xFFFFFFFFu, acc, o);
    if (lid == 0) out[row] = acc + g_bo[0];
}

// ----------------------------- launch ----------------------------------------
extern "C" void kernel_launch(void* const* d_in, const int* in_sizes, int n_in,
                              void* d_out, int out_size) {
    (void)in_sizes; (void)n_in; (void)out_size;
    cudaFuncSetAttribute(vn_gemm, cudaFuncAttributeMaxDynamicSharedMemorySize, SMEM_SIZE);

    // input order: x, w_mu_h, w_rho_h, b_mu_h, b_rho_h, w_mu_o, w_rho_o,
    //              b_mu_o, b_rho_o, eps_w_h, eps_b_h, eps_w_o, eps_b_o
    vn_mat_w<<<(HL * DIM * DIM / 4) / 256, 256>>>(
        (const float4*)d_in[1], (const float4*)d_in[2], (const float4*)d_in[9]);
    vn_mat_vec<<<(HL * DIM + 255) / 256, 256>>>(
        (const float*)d_in[3], (const float*)d_in[4], (const float*)d_in[10], 0, HL * DIM);
    vn_mat_vec<<<(DIM + 255) / 256, 256>>>(
        (const float*)d_in[5], (const float*)d_in[6], (const float*)d_in[11], 1, DIM);
    vn_mat_vec<<<1, 256>>>(
        (const float*)d_in[7], (const float*)d_in[8], (const float*)d_in[12], 2, 1);
    vn_x16<<<(BATCH * DIM / 4) / 256, 256>>>((const float4*)d_in[0]);

    dim3 grid(DIM / TNT, BATCH / TMT);   // (16, 32)
    vn_gemm<<<grid, 256, SMEM_SIZE>>>(0, 0, 0);   // A0 -> A1 (fp16)
    vn_gemm<<<grid, 256, SMEM_SIZE>>>(1, 1, 0);   // A1 -> A0 (fp16)
    vn_gemm<<<grid, 256, SMEM_SIZE>>>(2, 0, 1);   // A0 -> g_hf (fp32)

    vn_out<<<BATCH / 8, 256>>>((float*)d_out);
}